// round 9
// baseline (speedup 1.0000x reference)
#include <cuda_runtime.h>
#include <cuda_bf16.h>
#include <math.h>
#include <stdint.h>

#define N_NODES 10000
#define N_EDGES 320000
#define MUL 32

__device__ __align__(16) float g_wkv [N_EDGES * 256];   // per-edge MLP outputs [wk(128)|wv(128)]
__device__ __align__(16) float g_qpre[N_NODES * 1024];  // per-node precomputed query side
__device__ __align__(16) float g_z   [N_NODES * 4];     // attention normalizer per head
__device__ __align__(16) float g_agg [N_NODES * 256];   // unnormalized aggregation

#define INV3F 0.57735026918962576f
#define INVFAN 0.015625f

// ---------------------------------------------------------------- f32x2 helpers
__device__ __forceinline__ uint64_t pack2(float lo, float hi) {
    uint64_t r; asm("mov.b64 %0, {%1, %2};" : "=l"(r) : "f"(lo), "f"(hi)); return r;
}
__device__ __forceinline__ void unpack2(uint64_t v, float& lo, float& hi) {
    asm("mov.b64 {%0, %1}, %2;" : "=f"(lo), "=f"(hi) : "l"(v));
}
__device__ __forceinline__ void fmaX2(uint64_t& c, uint64_t a, uint64_t b) {
    asm("fma.rn.f32x2 %0, %1, %2, %0;" : "+l"(c) : "l"(a), "l"(b));
}

// ---------------------------------------------------------------- zero scratch
__global__ void ek_zero_kernel() {
    int i = blockIdx.x * blockDim.x + threadIdx.x;
    int stride = gridDim.x * blockDim.x;
    float4 z4 = make_float4(0.f, 0.f, 0.f, 0.f);
    for (int j = i; j < N_NODES * 64; j += stride) ((float4*)g_agg)[j] = z4;
    for (int j = i; j < N_NODES;      j += stride) ((float4*)g_z)[j]   = z4;
}

// ---------------------------------------------------------------- Qpre precompute
__global__ void __launch_bounds__(256) ek_qpre_kernel(const float* __restrict__ nodef,
                                                      const float* __restrict__ wdot,
                                                      int nbase) {
    extern __shared__ float qsm[];
    float* s_w = qsm;            // 16384 floats
    float* s_x = qsm + 16384;    // 128 floats
    int t = threadIdx.x;
    for (int i = t; i < 16384; i += 256) s_w[i] = wdot[i];
    for (int nn = 0; nn < 10; nn++) {
        int n = nbase + blockIdx.x * 10 + nn;
        __syncthreads();
        if (t < 32) *(float4*)&s_x[t * 4] = *(const float4*)(nodef + (size_t)n * 128 + t * 4);
        __syncthreads();
#pragma unroll
        for (int rep = 0; rep < 4; rep++) {
            int o = t + rep * 256;
            int h = o >> 8, i = o & 255;
            float acc = 0.f;
            if (i < 64) {
                int p = (i < 32) ? 0 : 1;
                int v = i & 31;
                const float* W = s_w + (p * 4 + h) * 1024 + v;
#pragma unroll
                for (int u = 0; u < 32; u++) acc += s_x[u] * W[u * 32];
                acc *= INVFAN;
            } else {
                int p  = (i < 160) ? 2 : 3;
                int tt = (i < 160) ? (i - 64) : (i - 160);
                int d = tt >> 5, v = tt & 31;
                const float* W = s_w + (p * 4 + h) * 1024 + v;
#pragma unroll
                for (int u = 0; u < 32; u++) acc += s_x[32 + 3 * u + d] * W[u * 32];
                acc *= INVFAN * INV3F;
            }
            g_qpre[(size_t)n * 1024 + o] = acc;
        }
    }
}

// ---------------------------------------------------------------- f32x2 dual MLP (part-split)
// grid (2500, 2): 128 edges x one part (0: wk outputs 0-127 from Hk, 1: wv).
// 512 threads. Layer1 scalar 8->64 (this part's hidden) + gelu into s_h[64k][128e].
// Layer2: C[128e][128n] = H^T W2, per-thread tile 4 edge-pairs x 4 outputs via
// fma.rn.f32x2. smem: s_h 32KB | s_w2[64k][128n] 32KB | w1 2KB | b1 256B.
#define MLP_SMEM 67840
__global__ void __launch_bounds__(512, 2) ek_mlp_kernel(const float* __restrict__ xattr,
    const float* __restrict__ wk1, const float* __restrict__ bk1, const float* __restrict__ wk2,
    const float* __restrict__ wv1, const float* __restrict__ bv1, const float* __restrict__ wv2) {
    extern __shared__ float sm[];
    float* s_h  = sm;            // [64][128]
    float* s_w2 = sm + 8192;     // [64][128]
    float* s_w1 = sm + 16384;    // [8][64]
    float* s_b1 = sm + 16896;    // [64]
    int t = threadIdx.x;
    int part = blockIdx.y;
    int e0 = blockIdx.x * 128;
    const float* w2g = part ? wv2 : wk2;
    const float* w1g = part ? wv1 : wk1;
    const float* b1g = part ? bv1 : bk1;

    for (int i = t; i < 8192; i += 512) s_w2[i] = w2g[i];   // [64][128] row-major direct copy
    if (t < 512) { if (t < 512) {} }
    for (int i = t; i < 512; i += 512) s_w1[i] = w1g[i];
    if (t < 64) s_b1[t] = b1g[t];
    __syncthreads();

    // layer1: e = t&127, quarter = t>>7 handles 16 channels
    {
        int e = t & 127, q4 = t >> 7;
        const float4* xp = (const float4*)(xattr + (size_t)(e0 + e) * 8);
        float4 xa = xp[0], xb = xp[1];
#pragma unroll 4
        for (int cc = 0; cc < 16; cc++) {
            int c = q4 * 16 + cc;
            float acc = xa.x * s_w1[c]       + xa.y * s_w1[64 + c]  + xa.z * s_w1[128 + c] + xa.w * s_w1[192 + c]
                      + xb.x * s_w1[256 + c] + xb.y * s_w1[320 + c] + xb.z * s_w1[384 + c] + xb.w * s_w1[448 + c];
            acc = acc * 0.35355339059327373f + s_b1[c];
            float u2 = 0.7978845608028654f * (acc + 0.044715f * acc * acc * acc);
            float th;
            asm("tanh.approx.f32 %0, %1;" : "=f"(th) : "f"(u2));
            s_h[c * 128 + e] = 0.5f * acc * (1.f + th);
        }
    }
    __syncthreads();

    // layer2: pt = t&15 -> 8 edges (4 pairs), ot = t>>4 -> 4 outputs
    int pt = t & 15, ot = t >> 4;
    const float* hp = s_h + pt * 8;
    const float* wp = s_w2 + ot * 4;
    uint64_t acc[4][4];
#pragma unroll
    for (int p = 0; p < 4; p++)
#pragma unroll
        for (int o = 0; o < 4; o++) acc[p][o] = 0ull;

#pragma unroll 8
    for (int k = 0; k < 64; k++) {
        ulonglong2 ha = *(const ulonglong2*)(hp + k * 128);      // edges pt*8+0..3 (2 pairs)
        ulonglong2 hb = *(const ulonglong2*)(hp + k * 128 + 4);  // edges pt*8+4..7
        float4 w4 = *(const float4*)(wp + k * 128);
        uint64_t hx[4] = { ha.x, ha.y, hb.x, hb.y };
        uint64_t wd[4] = { pack2(w4.x, w4.x), pack2(w4.y, w4.y),
                           pack2(w4.z, w4.z), pack2(w4.w, w4.w) };
#pragma unroll
        for (int p = 0; p < 4; p++)
#pragma unroll
            for (int o = 0; o < 4; o++) fmaX2(acc[p][o], hx[p], wd[o]);
    }

    const float inv64 = 0.125f;
    int colbase = part * 128 + ot * 4;
#pragma unroll
    for (int p = 0; p < 4; p++) {
        int elo = e0 + pt * 8 + p * 2;
        float lo[4], hi[4];
#pragma unroll
        for (int o = 0; o < 4; o++) { unpack2(acc[p][o], lo[o], hi[o]); lo[o] *= inv64; hi[o] *= inv64; }
        __stcs((float4*)(g_wkv + (size_t)elo * 256 + colbase),
               make_float4(lo[0], lo[1], lo[2], lo[3]));
        __stcs((float4*)(g_wkv + (size_t)(elo + 1) * 256 + colbase),
               make_float4(hi[0], hi[1], hi[2], hi[3]));
    }
}

// ---------------------------------------------------------------- edge megakernel (atomic, R6)
__device__ __forceinline__ float feat_base(int i, const float* row,
                                           float ys, float yv0, float yv1, float yv2,
                                           int& widx) {
    if (i < 32) { widx = i; return row[i] * ys; }
    if (i < 64) {
        int u = i - 32; widx = i;
        return (row[32 + 3 * u] * yv0 + row[33 + 3 * u] * yv1 + row[34 + 3 * u] * yv2) * INV3F;
    }
    if (i < 160) {
        int tt = i - 64; int d = tt >> 5, u = tt & 31; widx = 64 + u;
        float yd = (d == 0) ? yv0 : ((d == 1) ? yv1 : yv2);
        return row[u] * yd;
    }
    {
        int tt = i - 160; int d = tt >> 5, u = tt & 31; widx = 96 + u;
        return row[32 + 3 * u + d] * ys;
    }
}
__device__ __forceinline__ int feat_head(int i) {
    if (i < 64) return (i & 31) >> 3;
    int tt = (i < 160) ? (i - 64) : (i - 160);
    return (tt & 31) >> 3;
}
__device__ __forceinline__ void red_v4(float* p, float a, float b, float c, float d) {
    asm volatile("red.global.add.v4.f32 [%0], {%1, %2, %3, %4};"
                 :: "l"(p), "f"(a), "f"(b), "f"(c), "f"(d) : "memory");
}

__global__ void __launch_bounds__(256) ek_edge_kernel(
    const int* __restrict__ esrc, const int* __restrict__ edst,
    const float* __restrict__ eattr, const float* __restrict__ ecut,
    const float* __restrict__ nodef) {
    __shared__ float s_row[8][136];
    __shared__ float s_w[8][256];
    int warp = threadIdx.x >> 5, lane = threadIdx.x & 31;
    int e = blockIdx.x * 8 + warp;
    if (e >= N_EDGES) return;

    int s = esrc[e], dd = edst[e];
    float4 ea = *(const float4*)(eattr + (size_t)e * 4);
    float ys = ea.x, yv0 = ea.y, yv1 = ea.z, yv2 = ea.w;
    float cw = ecut[e];

    *(float4*)&s_row[warp][lane * 4] = *(const float4*)(nodef + (size_t)s * 128 + lane * 4);
    const float4* wv4 = (const float4*)(g_wkv + (size_t)e * 256);
    *(float4*)&s_w[warp][lane * 4]       = __ldcs(wv4 + lane);
    *(float4*)&s_w[warp][128 + lane * 4] = __ldcs(wv4 + 32 + lane);
    __syncwarp();

    const float* row = s_row[warp];
    const float* wk  = s_w[warp];
    int iA = 4 * lane, iB = 128 + 4 * lane;

    float bA[4], bB[4];
    int   xA[4], xB[4];
#pragma unroll
    for (int j = 0; j < 4; j++) {
        bA[j] = feat_base(iA + j, row, ys, yv0, yv1, yv2, xA[j]);
        bB[j] = feat_base(iB + j, row, ys, yv0, yv1, yv2, xB[j]);
    }

    float kA[4], kB[4];
#pragma unroll
    for (int j = 0; j < 4; j++) { kA[j] = wk[xA[j]] * bA[j]; kB[j] = wk[xB[j]] * bB[j]; }

    const float4* q = (const float4*)(g_qpre + (size_t)dd * 1024);
    float dh[4];
#pragma unroll
    for (int h = 0; h < 4; h++) {
        float4 qa = q[h * 64 + lane];
        float4 qb = q[h * 64 + 32 + lane];
        dh[h] = qa.x * kA[0] + qa.y * kA[1] + qa.z * kA[2] + qa.w * kA[3]
              + qb.x * kB[0] + qb.y * kB[1] + qb.z * kB[2] + qb.w * kB[3];
    }
#pragma unroll
    for (int off = 16; off; off >>= 1) {
#pragma unroll
        for (int h = 0; h < 4; h++) dh[h] += __shfl_xor_sync(0xffffffffu, dh[h], off);
    }

    float ew[4], sa[4];
#pragma unroll
    for (int h = 0; h < 4; h++) {
        ew[h] = cw * expf(dh[h]);
        sa[h] = sqrtf(ew[h]);     // sqrt(expw); /sqrt(z) deferred to epilogue
    }
    if (lane == 0) red_v4(g_z + (size_t)dd * 4, ew[0], ew[1], ew[2], ew[3]);

    const float* wv = wk + 128;
    float vA[4], vB[4];
#pragma unroll
    for (int j = 0; j < 4; j++) {
        vA[j] = wv[xA[j]] * bA[j] * sa[feat_head(iA + j)];
        vB[j] = wv[xB[j]] * bB[j] * sa[feat_head(iB + j)];
    }
    red_v4(g_agg + (size_t)dd * 256 + iA, vA[0], vA[1], vA[2], vA[3]);
    red_v4(g_agg + (size_t)dd * 256 + iB, vB[0], vB[1], vB[2], vB[3]);
}

// ---------------------------------------------------------------- node epilogue
__global__ void __launch_bounds__(128) ek_out_kernel(const float* __restrict__ wls,
                                                     const float* __restrict__ wlv,
                                                     float* __restrict__ out) {
    __shared__ float s_ws[2048];
    __shared__ float s_wv[2048];
    __shared__ float s_s[64];
    __shared__ float s_v[192];
    __shared__ float s_sc[4];
    int t = threadIdx.x;
    for (int i = t; i < 2048; i += 128) { s_ws[i] = wls[i]; s_wv[i] = wlv[i]; }
    const float inv_l = 0.125f;

    for (int nn = 0; nn < 10; nn++) {
        int n = blockIdx.x * 10 + nn;
        __syncthreads();
        if (t < 4) {
            float zz = g_z[(size_t)n * 4 + t];
            s_sc[t] = (zz == 0.f) ? 1.f : (1.0f / sqrtf(zz));
        }
        __syncthreads();
        for (int i = t; i < 256; i += 128) {
            float val = g_agg[(size_t)n * 256 + i];
            if (i < 64) {
                s_s[i] = val * s_sc[(i & 31) >> 3];
            } else {
                int f = i - 64;
                int blk = (f < 96) ? 0 : 1;
                int r = f - blk * 96;
                int d = r >> 5, uu = r & 31;
                s_v[d * 64 + blk * 32 + uu] = val * s_sc[uu >> 3];
            }
        }
        __syncthreads();
        if (t < 32) {
            int w = t;
            float acc = 0.f;
#pragma unroll
            for (int u = 0; u < 64; u++) acc += s_s[u] * s_ws[u * 32 + w];
            out[(size_t)n * 128 + w] = acc * inv_l;
        } else {
            int o = t - 32;
            int d = o >> 5, w = o & 31;
            float acc = 0.f;
#pragma unroll
            for (int u = 0; u < 64; u++) acc += s_v[d * 64 + u] * s_wv[u * 32 + w];
            out[(size_t)n * 128 + 32 + w * 3 + d] = acc * inv_l;
        }
    }
}

// ---------------------------------------------------------------- launch
extern "C" void kernel_launch(void* const* d_in, const int* in_sizes, int n_in,
                              void* d_out, int out_size) {
    const int*   esrc  = (const int*)d_in[0];
    const int*   edst  = (const int*)d_in[1];
    const float* xattr = (const float*)d_in[2];
    const float* eattr = (const float*)d_in[3];
    const float* ecut  = (const float*)d_in[4];
    const float* nodef = (const float*)d_in[5];
    const float* wk1   = (const float*)d_in[6];
    const float* bk1   = (const float*)d_in[7];
    const float* wk2   = (const float*)d_in[8];
    const float* wv1   = (const float*)d_in[9];
    const float* bv1   = (const float*)d_in[10];
    const float* wv2   = (const float*)d_in[11];
    const float* wdot  = (const float*)d_in[12];
    const float* wls   = (const float*)d_in[13];
    const float* wlv   = (const float*)d_in[14];
    float* out = (float*)d_out;

    const int qpre_smem = 16512 * 4;   // 66,048 B
    cudaFuncSetAttribute(ek_qpre_kernel, cudaFuncAttributeMaxDynamicSharedMemorySize, qpre_smem);
    cudaFuncSetAttribute(ek_mlp_kernel,  cudaFuncAttributeMaxDynamicSharedMemorySize, MLP_SMEM);

    // launch index 3 (ncu capture slot) = ek_mlp_kernel
    ek_zero_kernel<<<1024, 256>>>();
    ek_qpre_kernel<<<500, 256, qpre_smem>>>(nodef, wdot, 0);
    ek_qpre_kernel<<<500, 256, qpre_smem>>>(nodef, wdot, 5000);
    dim3 mgrid(N_EDGES / 128, 2);
    ek_mlp_kernel<<<mgrid, 512, MLP_SMEM>>>(xattr, wk1, bk1, wk2, wv1, bv1, wv2);
    ek_edge_kernel<<<N_EDGES / 8, 256>>>(esrc, edst, eattr, ecut, nodef);
    ek_out_kernel<<<N_NODES / 10, 128>>>(wls, wlv, out);
}